// round 14
// baseline (speedup 1.0000x reference)
#include <cuda_runtime.h>
#include <cuda_fp16.h>
#include <cstdint>

// TopKNoisyRouter: fused dual GEMM [N,1024]x[1024,128], fp16 2-way split
// (3 HMMA products, fp32 accum, W pre-scaled by 32). KC=64 variant of r12:
// 16 chunks, A single-buffered (2 planes, native 128B-row SW128), B 2-buf
// (cp.async dist 1, covered by the 2x-long MMA region). Two barriers per
// chunk (32 total, same as r12) but 192-HMMA uninterrupted MMA runs.
// x: first half prefetched in regs under prior MMA; second half via early
// LDGs overlapped with wait+convert. 4-way k-step stagger by wq.
// 2 CTAs/SM. Fused noisy-top-2 + softmax epilogue.

#define DK 1024
#define NE 64
#define BM 128
#define KC 64
#define NCHUNK (DK / KC)      // 16
#define PLANE 16384           // 128 rows x 64 fp16 (128B rows)
#define OFF_B (2 * PLANE)     // A: 2 planes at 0; B: 2 bufs x 2 planes at 32768
#define SMEM_BYTES 100352     // gemm needs 98304; epilogue 100352

__device__ __half g_w[2][128 * DK];   // fp16(32w), fp16(32w - hi); K-major

__device__ __forceinline__ uint32_t smem_u32(const void* p) {
    uint32_t a;
    asm("{ .reg .u64 t; cvta.to.shared.u64 t, %1; cvt.u32.u64 %0, t; }" : "=r"(a) : "l"(p));
    return a;
}
__device__ __forceinline__ void cp16(uint32_t dst, const void* src) {
    asm volatile("cp.async.cg.shared.global [%0], [%1], 16;" :: "r"(dst), "l"(src));
}
__device__ __forceinline__ void ldsm4(uint32_t& r0, uint32_t& r1, uint32_t& r2,
                                      uint32_t& r3, uint32_t addr) {
    asm volatile("ldmatrix.sync.aligned.m8n8.x4.shared.b16 {%0,%1,%2,%3}, [%4];"
                 : "=r"(r0), "=r"(r1), "=r"(r2), "=r"(r3) : "r"(addr));
}
__device__ __forceinline__ void mma16816(float* c, const uint32_t* a,
                                         uint32_t b0, uint32_t b1) {
    asm volatile("mma.sync.aligned.m16n8k16.row.col.f32.f16.f16.f32 "
                 "{%0,%1,%2,%3}, {%4,%5,%6,%7}, {%8,%9}, {%0,%1,%2,%3};"
                 : "+f"(c[0]), "+f"(c[1]), "+f"(c[2]), "+f"(c[3])
                 : "r"(a[0]), "r"(a[1]), "r"(a[2]), "r"(a[3]), "r"(b0), "r"(b1));
}
__device__ __forceinline__ float softplusf(float v) {
    return fmaxf(v, 0.0f) + log1pf(expf(-fabsf(v)));
}
__device__ __forceinline__ uint32_t h2u(__half2 h) {
    union { __half2 h; uint32_t u; } v; v.h = h; return v.u;
}

__global__ void prep_weights(const float* __restrict__ wr, const float* __restrict__ wn) {
    int i = blockIdx.x * blockDim.x + threadIdx.x;    // 0 .. 128*1024-1
    int e = i >> 10, k = i & 1023;
    float v = 32.0f * ((e < NE) ? wr[e * DK + k] : wn[(e - NE) * DK + k]);
    __half h = __float2half_rn(v);
    g_w[0][i] = h;
    g_w[1][i] = __float2half_rn(v - __half2float(h));
}

// convert 16 floats (4x float4) -> 2x uint4 hi + 2x uint4 lo, store to A
__device__ __forceinline__ void cvt_store16(char* Abase, uint32_t off0, uint32_t off1,
                                            float4 f0, float4 f1, float4 f2, float4 f3)
{
    __half2 a0 = __floats2half2_rn(f0.x, f0.y);
    __half2 a1 = __floats2half2_rn(f0.z, f0.w);
    __half2 a2 = __floats2half2_rn(f1.x, f1.y);
    __half2 a3 = __floats2half2_rn(f1.z, f1.w);
    __half2 a4 = __floats2half2_rn(f2.x, f2.y);
    __half2 a5 = __floats2half2_rn(f2.z, f2.w);
    __half2 a6 = __floats2half2_rn(f3.x, f3.y);
    __half2 a7 = __floats2half2_rn(f3.z, f3.w);
    float2 g0 = __half22float2(a0), g1 = __half22float2(a1);
    float2 g2 = __half22float2(a2), g3 = __half22float2(a3);
    float2 g4 = __half22float2(a4), g5 = __half22float2(a5);
    float2 g6 = __half22float2(a6), g7 = __half22float2(a7);
    *(uint4*)(Abase + off0) = make_uint4(h2u(a0), h2u(a1), h2u(a2), h2u(a3));
    *(uint4*)(Abase + off1) = make_uint4(h2u(a4), h2u(a5), h2u(a6), h2u(a7));
    *(uint4*)(Abase + PLANE + off0) = make_uint4(
        h2u(__floats2half2_rn(f0.x - g0.x, f0.y - g0.y)),
        h2u(__floats2half2_rn(f0.z - g1.x, f0.w - g1.y)),
        h2u(__floats2half2_rn(f1.x - g2.x, f1.y - g2.y)),
        h2u(__floats2half2_rn(f1.z - g3.x, f1.w - g3.y)));
    *(uint4*)(Abase + PLANE + off1) = make_uint4(
        h2u(__floats2half2_rn(f2.x - g4.x, f2.y - g4.y)),
        h2u(__floats2half2_rn(f2.z - g5.x, f2.w - g5.y)),
        h2u(__floats2half2_rn(f3.x - g6.x, f3.y - g6.y)),
        h2u(__floats2half2_rn(f3.z - g7.x, f3.w - g7.y)));
}

__global__ __launch_bounds__(256, 2)
void router_gemm(const float* __restrict__ x, const float* __restrict__ eps,
                 float* __restrict__ out, float* __restrict__ idx_out, int write_idx)
{
    extern __shared__ char smem[];
    const uint32_t sb = smem_u32(smem);
    const int tid = threadIdx.x;
    const int lane = tid & 31, wid = tid >> 5;
    const int wm = wid & 1, wq = wid >> 1;        // warp tile 64x32 at (wm*64, wq*32)
    const int row0 = blockIdx.x * BM;

    // coalesced zero-fill of this block's output tile [128 x 64]
    {
        float4 z = make_float4(0.f, 0.f, 0.f, 0.f);
        float4* ot = (float4*)(out + (size_t)row0 * NE);
        #pragma unroll
        for (int i = 0; i < 8; ++i) ot[tid + 256 * i] = z;
    }

    // ldmatrix per-lane address pieces (native 128B-row SW128)
    const int rA = wm * 64 + (lane & 15);
    const uint32_t rowA = (uint32_t)(rA * 128);
    const uint32_t xorA = (uint32_t)((rA & 7) << 4);
    const uint32_t cbA  = (uint32_t)((lane >> 4) * 16);
    const int rB = wq * 32 + (lane & 7) + ((lane >> 4) << 3);
    const uint32_t rowB = (uint32_t)(rB * 128);
    const uint32_t xorB = (uint32_t)((rB & 7) << 4);
    const uint32_t cbB  = (uint32_t)(((lane >> 3) & 1) * 16);
    const int ksw = wq;          // 4-way k-step stagger

    // x: thread covers row r_x, cols h_x..h_x+31 of each 64-col chunk
    const int r_x = tid >> 1;
    const int h_x = (tid & 1) * 32;
    const float* xbase = x + (size_t)(row0 + r_x) * DK + h_x;
    const uint32_t xr7 = (uint32_t)((r_x & 7) << 4);
    const uint32_t rbX = (uint32_t)(r_x * 128);
    const uint32_t of0 = rbX + (((uint32_t)(h_x * 2) +  0) ^ xr7);
    const uint32_t of1 = rbX + (((uint32_t)(h_x * 2) + 16) ^ xr7);
    const uint32_t of2 = rbX + (((uint32_t)(h_x * 2) + 32) ^ xr7);
    const uint32_t of3 = rbX + (((uint32_t)(h_x * 2) + 48) ^ xr7);

    // hoisted B cp.async addressing: thread -> (n0, ku); copies at constant strides
    const int n0 = tid >> 3, ku = tid & 7;
    const uint32_t bd0 = sb + OFF_B +
        (uint32_t)(n0 * 128) + (((uint32_t)(ku * 16)) ^ ((uint32_t)((n0 & 7) << 4)));
    const __half* bs0 = &g_w[0][n0 * DK + ku * 8];

    float acc[4][4][4];
    #pragma unroll
    for (int mt = 0; mt < 4; ++mt)
        #pragma unroll
        for (int nt = 0; nt < 4; ++nt)
            #pragma unroll
            for (int q = 0; q < 4; ++q) acc[mt][nt][q] = 0.f;

    // ---- prologue: x chunk0 first half -> regs; B chunk0 -> cp.async ----
    float4 xr[4];
    #pragma unroll
    for (int i = 0; i < 4; ++i) xr[i] = *(const float4*)(xbase + 4 * i);
    #pragma unroll
    for (int s = 0; s < 2; ++s)
        #pragma unroll
        for (int j = 0; j < 4; ++j)
            cp16(bd0 + (uint32_t)s * PLANE + (uint32_t)j * 4096,
                 bs0 + (s * 128 + j * 32) * DK);
    asm volatile("cp.async.commit_group;" ::: "memory");

    #pragma unroll 1
    for (int c = 0; c < NCHUNK; ++c) {
        const int b = c & 1;
        const int kc = c * KC;

        // ---- early-issue second-half x loads (latency overlaps wait+cvt) ----
        float4 y0 = *(const float4*)(xbase + kc + 16);
        float4 y1 = *(const float4*)(xbase + kc + 20);
        float4 y2 = *(const float4*)(xbase + kc + 24);
        float4 y3 = *(const float4*)(xbase + kc + 28);

        // convert first half (xr) -> A planes
        cvt_store16(smem, of0, of1, xr[0], xr[1], xr[2], xr[3]);

        // B chunk c complete for THIS thread
        asm volatile("cp.async.wait_group 0;" ::: "memory");

        // convert second half -> A planes
        cvt_store16(smem, of2, of3, y0, y1, y2, y3);

        __syncthreads();                         // publish A + B[b]

        // ---- issue B chunk c+1 into buffer 1-b (read finished in MMA(c-1)) ----
        if (c + 1 < NCHUNK) {
            const __half* bsk = bs0 + kc + KC;
            const uint32_t bb = (uint32_t)((1 - b) * 2) * PLANE;
            #pragma unroll
            for (int s = 0; s < 2; ++s)
                #pragma unroll
                for (int j = 0; j < 4; ++j)
                    cp16(bd0 + bb + (uint32_t)s * PLANE + (uint32_t)j * 4096,
                         bsk + (s * 128 + j * 32) * DK);
            asm volatile("cp.async.commit_group;" ::: "memory");
        }
        // ---- prefetch x chunk c+1 first half (hidden under MMA) ----
        {
            const int kn = ((c + 1) & (NCHUNK - 1)) * KC;   // wraps, safe
            #pragma unroll
            for (int i = 0; i < 4; ++i) xr[i] = *(const float4*)(xbase + kn + 4 * i);
        }

        // ---- MMA: 3 split products over 4 k16 steps, wq-staggered ----
        const uint32_t Ah = sb;
        const uint32_t Al = sb + PLANE;
        const uint32_t Bh = sb + OFF_B + (uint32_t)(b * 2) * PLANE;
        const uint32_t Bl = Bh + PLANE;
        #pragma unroll
        for (int t = 0; t < 4; ++t) {
            const int ks = (t + ksw) & 3;
            const uint32_t kb = (uint32_t)(ks * 32);
            const uint32_t ca = (kb + cbA) ^ xorA;
            const uint32_t cc = (kb + cbB) ^ xorB;
            uint32_t a[4][4], bh[8], bl[8];
            // loads for hh + hl up front, then alternate mma groups
            #pragma unroll
            for (int mt = 0; mt < 4; ++mt)
                ldsm4(a[mt][0], a[mt][1], a[mt][2], a[mt][3], Ah + rowA + mt * 2048 + ca);
            ldsm4(bh[0], bh[1], bh[2], bh[3], Bh + rowB + cc);
            ldsm4(bh[4], bh[5], bh[6], bh[7], Bh + rowB + 2048 + cc);
            ldsm4(bl[0], bl[1], bl[2], bl[3], Bl + rowB + cc);
            ldsm4(bl[4], bl[5], bl[6], bl[7], Bl + rowB + 2048 + cc);
            #pragma unroll
            for (int mt = 0; mt < 4; ++mt)
                #pragma unroll
                for (int nt = 0; nt < 4; ++nt)
                    mma16816(acc[mt][nt], a[mt], bh[2 * nt], bh[2 * nt + 1]);
            #pragma unroll
            for (int mt = 0; mt < 4; ++mt)
                #pragma unroll
                for (int nt = 0; nt < 4; ++nt)
                    mma16816(acc[mt][nt], a[mt], bl[2 * nt], bl[2 * nt + 1]);
            #pragma unroll
            for (int mt = 0; mt < 4; ++mt)
                ldsm4(a[mt][0], a[mt][1], a[mt][2], a[mt][3], Al + rowA + mt * 2048 + ca);
            #pragma unroll
            for (int mt = 0; mt < 4; ++mt)
                #pragma unroll
                for (int nt = 0; nt < 4; ++nt)
                    mma16816(acc[mt][nt], a[mt], bh[2 * nt], bh[2 * nt + 1]);
        }

        __syncthreads();                         // A free for next convert
    }

    // ---- stage C (scaled 1/32) + eps to smem, fused top-2 epilogue ----
    float* Cs = (float*)smem;                    // [128][130]
    float* Es = (float*)(smem + 66560);          // [128][66]
    {
        const float INV32 = 0.03125f;
        const int crow = wm * 64 + (lane >> 2);
        const int ccol = wq * 32 + (lane & 3) * 2;
        #pragma unroll
        for (int mt = 0; mt < 4; ++mt)
            #pragma unroll
            for (int nt = 0; nt < 4; ++nt) {
                float* p0 = Cs + (crow + mt * 16) * 130 + ccol + nt * 8;
                p0[0] = acc[mt][nt][0] * INV32; p0[1] = acc[mt][nt][1] * INV32;
                float* p1 = p0 + 8 * 130;
                p1[0] = acc[mt][nt][2] * INV32; p1[1] = acc[mt][nt][3] * INV32;
            }
        const float4* eg = (const float4*)(eps + (size_t)row0 * NE);
        #pragma unroll
        for (int i4 = 0; i4 < 8; ++i4) {
            int u = tid + 256 * i4;                 // 0..2047
            float4 v = eg[u];
            int r = u >> 4, e = (u & 15) * 4;
            float* d = Es + r * 66 + e;
            d[0] = v.x; d[1] = v.y; d[2] = v.z; d[3] = v.w;
        }
    }
    __syncthreads();

    if (tid < BM) {
        const int r = tid;
        const size_t n = (size_t)row0 + r;
        const float* lg = Cs + r * 130;
        const float* er = Es + r * 66;
        const float NEG = __int_as_float(0xff800000);
        float m1 = NEG, m2 = NEG; int i1 = 0, i2 = 0;
        #pragma unroll
        for (int e = 0; e < NE; ++e) {
            float v = lg[e] + er[e] * softplusf(lg[e + 64]);
            if (v > m1) { m2 = m1; i2 = i1; m1 = v; i1 = e; }
            else if (v > m2) { m2 = v; i2 = e; }
        }
        float ee = expf(m2 - m1);
        float inv = 1.0f / (1.0f + ee);
        out[n * NE + i1] = inv;
        out[n * NE + i2] = ee * inv;
        if (write_idx) {
            idx_out[n * 2 + 0] = (float)i1;
            idx_out[n * 2 + 1] = (float)i2;
        }
    }
}

extern "C" void kernel_launch(void* const* d_in, const int* in_sizes, int n_in,
                              void* d_out, int out_size)
{
    const float* x   = (const float*)d_in[0];
    const float* wr  = (const float*)d_in[1];
    const float* wn  = (const float*)d_in[2];
    const float* eps = (const float*)d_in[3];
    float* out = (float*)d_out;

    const int N = in_sizes[3] / NE;
    const int write_idx = (out_size >= N * NE + N * 2) ? 1 : 0;
    float* idx_out = out + (size_t)N * NE;

    prep_weights<<<(128 * DK) / 256, 256>>>(wr, wn);

    cudaFuncSetAttribute(router_gemm,
                         cudaFuncAttributeMaxDynamicSharedMemorySize, SMEM_BYTES);
    router_gemm<<<N / BM, 256, SMEM_BYTES>>>(x, eps, out, idx_out, write_idx);
}

// round 15
// speedup vs baseline: 1.0746x; 1.0746x over previous
#include <cuda_runtime.h>
#include <cuda_fp16.h>
#include <cstdint>

// TopKNoisyRouter: fused dual GEMM [N,1024]x[1024,128], fp16 2-way split
// (3 HMMA products, fp32 accum, W pre-scaled by 32). r12 mainloop verbatim
// (KC=32, A 2-buf, B 3-buf ring at cp.async distance 2, warp-parity k-step
// stagger, ldsm/MMA interleave, hoisted cp.async addressing). Changes:
//  - single-write output: no startup zero-fill; epilogue assembles the
//    [128][64] block in smem and stores it once, coalesced.
//  - B cp.async uses .ca (L1-cached) for cross-CTA weight reuse on the SM.
//  - prep_weights vectorized (float4, 4 elems/thread).
// 2 CTAs/SM. Fused noisy-top-2 + softmax epilogue.

#define DK 1024
#define NE 64
#define BM 128
#define KC 32
#define NCHUNK (DK / KC)      // 32
#define PLANE 8192            // 128 rows x 32 fp16 (64B rows)
#define OFF_B (4 * PLANE)     // A: 2 bufs x 2 planes; B: 3 bufs x 2 planes
#define SMEM_BYTES 100352     // max(gemm 80KB, epilogue staging)

__device__ __half g_w[2][128 * DK];   // fp16(32w), fp16(32w - hi); K-major

__device__ __forceinline__ uint32_t smem_u32(const void* p) {
    uint32_t a;
    asm("{ .reg .u64 t; cvta.to.shared.u64 t, %1; cvt.u32.u64 %0, t; }" : "=r"(a) : "l"(p));
    return a;
}
__device__ __forceinline__ uint32_t swz32(uint32_t r, uint32_t c) {
    return (r >> 1) * 128 + (r & 1) * 64 + (c ^ (((r >> 1) & 3) << 4));
}
__device__ __forceinline__ void cp16ca(uint32_t dst, const void* src) {
    asm volatile("cp.async.ca.shared.global [%0], [%1], 16;" :: "r"(dst), "l"(src));
}
__device__ __forceinline__ void ldsm4(uint32_t& r0, uint32_t& r1, uint32_t& r2,
                                      uint32_t& r3, uint32_t addr) {
    asm volatile("ldmatrix.sync.aligned.m8n8.x4.shared.b16 {%0,%1,%2,%3}, [%4];"
                 : "=r"(r0), "=r"(r1), "=r"(r2), "=r"(r3) : "r"(addr));
}
__device__ __forceinline__ void mma16816(float* c, const uint32_t* a,
                                         uint32_t b0, uint32_t b1) {
    asm volatile("mma.sync.aligned.m16n8k16.row.col.f32.f16.f16.f32 "
                 "{%0,%1,%2,%3}, {%4,%5,%6,%7}, {%8,%9}, {%0,%1,%2,%3};"
                 : "+f"(c[0]), "+f"(c[1]), "+f"(c[2]), "+f"(c[3])
                 : "r"(a[0]), "r"(a[1]), "r"(a[2]), "r"(a[3]), "r"(b0), "r"(b1));
}
__device__ __forceinline__ float softplusf(float v) {
    return fmaxf(v, 0.0f) + log1pf(expf(-fabsf(v)));
}
__device__ __forceinline__ uint32_t h2u(__half2 h) {
    union { __half2 h; uint32_t u; } v; v.h = h; return v.u;
}

__global__ void prep_weights(const float* __restrict__ wr, const float* __restrict__ wn) {
    int i4 = blockIdx.x * blockDim.x + threadIdx.x;   // 0 .. 32767 (x4 elems)
    int i = i4 * 4;
    int e = i >> 10, k = i & 1023;
    const float* src = (e < NE) ? (wr + e * DK + k) : (wn + (e - NE) * DK + k);
    float4 v4 = *(const float4*)src;
    float f[4] = {32.f * v4.x, 32.f * v4.y, 32.f * v4.z, 32.f * v4.w};
    __half h[4], l[4];
    #pragma unroll
    for (int j = 0; j < 4; ++j) {
        h[j] = __float2half_rn(f[j]);
        l[j] = __float2half_rn(f[j] - __half2float(h[j]));
    }
    *(uint2*)&g_w[0][i] = make_uint2(
        (uint32_t)__half_as_ushort(h[0]) | ((uint32_t)__half_as_ushort(h[1]) << 16),
        (uint32_t)__half_as_ushort(h[2]) | ((uint32_t)__half_as_ushort(h[3]) << 16));
    *(uint2*)&g_w[1][i] = make_uint2(
        (uint32_t)__half_as_ushort(l[0]) | ((uint32_t)__half_as_ushort(l[1]) << 16),
        (uint32_t)__half_as_ushort(l[2]) | ((uint32_t)__half_as_ushort(l[3]) << 16));
}

__global__ __launch_bounds__(256, 2)
void router_gemm(const float* __restrict__ x, const float* __restrict__ eps,
                 float* __restrict__ out, float* __restrict__ idx_out, int write_idx)
{
    extern __shared__ char smem[];
    const uint32_t sb = smem_u32(smem);
    const int tid = threadIdx.x;
    const int lane = tid & 31, wid = tid >> 5;
    const int wm = wid & 1, wq = wid >> 1;        // warp tile 64x32 at (wm*64, wq*32)
    const int row0 = blockIdx.x * BM;

    // ldmatrix per-lane address pieces
    const int rA = wm * 64 + (lane & 15);
    const uint32_t rowA = (uint32_t)((rA >> 1) * 128 + (rA & 1) * 64);
    const uint32_t xorA = (uint32_t)(((rA >> 1) & 3) << 4);
    const uint32_t cbA  = (uint32_t)((lane >> 4) * 16);
    const int rB = wq * 32 + (lane & 7) + ((lane >> 4) << 3);
    const uint32_t rowB = (uint32_t)((rB >> 1) * 128 + (rB & 1) * 64);
    const uint32_t xorB = (uint32_t)(((rB >> 1) & 3) << 4);
    const uint32_t cbB  = (uint32_t)(((lane >> 3) & 1) * 16);
    const int ksw = wid & 1;     // k-step stagger parity

    // x staging: thread covers row r_x, 16 floats at float-offset h_x
    const int r_x = tid >> 1;
    const int h_x = (tid & 1) * 16;
    const float* xbase = x + (size_t)(row0 + r_x) * DK + h_x;
    const uint32_t rowX = (uint32_t)((r_x >> 1) * 128 + (r_x & 1) * 64);
    const uint32_t xorX = (uint32_t)(((r_x >> 1) & 3) << 4);
    const uint32_t swX0 = rowX + (((uint32_t)(h_x * 2) +  0) ^ xorX);
    const uint32_t swX1 = rowX + (((uint32_t)(h_x * 2) + 16) ^ xorX);

    // hoisted cp.async per-thread addressing (4 copies of 16B per chunk)
    uint32_t bdst[4];
    const __half* bsrc[4];
    #pragma unroll
    for (int j = 0; j < 4; ++j) {
        const int u = tid + 256 * j;             // 0..1023
        const int s = u >> 9, rem = u & 511;
        const int n = rem >> 2, cu = (rem & 3) * 16;
        bdst[j] = sb + OFF_B + (uint32_t)s * PLANE + swz32((uint32_t)n, (uint32_t)cu);
        bsrc[j] = &g_w[s][n * DK + (cu >> 1)];
    }

    float acc[4][4][4];
    #pragma unroll
    for (int mt = 0; mt < 4; ++mt)
        #pragma unroll
        for (int nt = 0; nt < 4; ++nt)
            #pragma unroll
            for (int q = 0; q < 4; ++q) acc[mt][nt][q] = 0.f;

    // ---- prologue: x chunk0 -> regs; B chunks 0,1 -> cp.async (2 groups) ----
    float4 xr[4];
    #pragma unroll
    for (int i = 0; i < 4; ++i) xr[i] = *(const float4*)(xbase + 4 * i);
    #pragma unroll
    for (int j = 0; j < 4; ++j) cp16ca(bdst[j], bsrc[j]);
    asm volatile("cp.async.commit_group;" ::: "memory");
    #pragma unroll
    for (int j = 0; j < 4; ++j) cp16ca(bdst[j] + 2 * PLANE, bsrc[j] + KC);
    asm volatile("cp.async.commit_group;" ::: "memory");

    int br = 0;   // B read buffer (c % 3)
    int bp = 2;   // B prefetch buffer ((c+2) % 3)

    #pragma unroll 1
    for (int c = 0; c < NCHUNK; ++c) {
        const int b = c & 1;
        const int kn = ((c + 1) & (NCHUNK - 1)) * KC;   // next x chunk (wraps, safe)
        char* Ab = smem + (uint32_t)(b * 2) * PLANE;

        // ---- convert x regs (chunk c) -> A[b] (packed f16x2, STS.128);
        //      prefetch next x into regs ----
        {
            uint32_t hh[8], hl[8];
            #pragma unroll
            for (int i = 0; i < 4; ++i) {
                float4 f4 = xr[i];
                xr[i] = *(const float4*)(xbase + kn + 4 * i);
                __half2 a2 = __floats2half2_rn(f4.x, f4.y);
                __half2 b2 = __floats2half2_rn(f4.z, f4.w);
                float2 fa = __half22float2(a2), fb = __half22float2(b2);
                hh[2 * i]     = h2u(a2);
                hh[2 * i + 1] = h2u(b2);
                hl[2 * i]     = h2u(__floats2half2_rn(f4.x - fa.x, f4.y - fa.y));
                hl[2 * i + 1] = h2u(__floats2half2_rn(f4.z - fb.x, f4.w - fb.y));
            }
            *(uint4*)(Ab + swX0)         = make_uint4(hh[0], hh[1], hh[2], hh[3]);
            *(uint4*)(Ab + swX1)         = make_uint4(hh[4], hh[5], hh[6], hh[7]);
            *(uint4*)(Ab + PLANE + swX0) = make_uint4(hl[0], hl[1], hl[2], hl[3]);
            *(uint4*)(Ab + PLANE + swX1) = make_uint4(hl[4], hl[5], hl[6], hl[7]);
        }

        // B group for chunk c complete for THIS thread, then publish.
        asm volatile("cp.async.wait_group 1;" ::: "memory");
        __syncthreads();                         // A[b] + B[br] visible

        // ---- issue B chunk c+2 into buffer bp; commit ALWAYS (empty on
        //      tail) to keep group accounting exact ----
        if (c + 2 < NCHUNK) {
            const int kB = (c + 2) * KC;
            const uint32_t bb = (uint32_t)(bp * 2) * PLANE;
            #pragma unroll
            for (int j = 0; j < 4; ++j) cp16ca(bdst[j] + bb, bsrc[j] + kB);
        }
        asm volatile("cp.async.commit_group;" ::: "memory");

        // ---- MMA: 3 split products over 2 k16 steps, staggered by warp
        //      parity; ldsm groups interleaved with MMA groups ----
        const uint32_t Ah = sb + (uint32_t)(b * 2) * PLANE;
        const uint32_t Al = Ah + PLANE;
        const uint32_t Bh = sb + OFF_B + (uint32_t)(br * 2) * PLANE;
        const uint32_t Bl = Bh + PLANE;
        #pragma unroll
        for (int t = 0; t < 2; ++t) {
            const int ks = t ^ ksw;              // even warps 0,1; odd 1,0
            const uint32_t kb = (uint32_t)(ks * 32);
            const uint32_t ca = (kb + cbA) ^ xorA;
            const uint32_t cc = (kb + cbB) ^ xorB;
            uint32_t a[4][4], bh[8], bl[8];
            // group 1: A-hi + B-hi, then hh product
            #pragma unroll
            for (int mt = 0; mt < 4; ++mt)
                ldsm4(a[mt][0], a[mt][1], a[mt][2], a[mt][3], Ah + rowA + mt * 1024 + ca);
            ldsm4(bh[0], bh[1], bh[2], bh[3], Bh + rowB + cc);
            ldsm4(bh[4], bh[5], bh[6], bh[7], Bh + rowB + 1024 + cc);
            #pragma unroll
            for (int mt = 0; mt < 4; ++mt)
                #pragma unroll
                for (int nt = 0; nt < 4; ++nt)
                    mma16816(acc[mt][nt], a[mt], bh[2 * nt], bh[2 * nt + 1]);
            // group 2: B-lo, then hl product
            ldsm4(bl[0], bl[1], bl[2], bl[3], Bl + rowB + cc);
            ldsm4(bl[4], bl[5], bl[6], bl[7], Bl + rowB + 1024 + cc);
            #pragma unroll
            for (int mt = 0; mt < 4; ++mt)
                #pragma unroll
                for (int nt = 0; nt < 4; ++nt)
                    mma16816(acc[mt][nt], a[mt], bl[2 * nt], bl[2 * nt + 1]);
            // group 3: A-lo, then lh product
            #pragma unroll
            for (int mt = 0; mt < 4; ++mt)
                ldsm4(a[mt][0], a[mt][1], a[mt][2], a[mt][3], Al + rowA + mt * 1024 + ca);
            #pragma unroll
            for (int mt = 0; mt < 4; ++mt)
                #pragma unroll
                for (int nt = 0; nt < 4; ++nt)
                    mma16816(acc[mt][nt], a[mt], bh[2 * nt], bh[2 * nt + 1]);
        }

        br = (br == 2) ? 0 : br + 1;
        bp = (bp == 2) ? 0 : bp + 1;
    }
    __syncthreads();

    // ---- epilogue: stage C (scaled 1/32) + eps, top-2, then single-write
    //      of the fully-assembled [128][64] output block ----
    float* Cs = (float*)smem;                    // [128][130] = 66560 B
    float* Es = (float*)(smem + 66560);          // [128][66]  = 33792 B
    {
        const float INV32 = 0.03125f;
        const int crow = wm * 64 + (lane >> 2);
        const int ccol = wq * 32 + (lane & 3) * 2;
        #pragma unroll
        for (int mt = 0; mt < 4; ++mt)
            #pragma unroll
            for (int nt = 0; nt < 4; ++nt) {
                float* p0 = Cs + (crow + mt * 16) * 130 + ccol + nt * 8;
                p0[0] = acc[mt][nt][0] * INV32; p0[1] = acc[mt][nt][1] * INV32;
                float* p1 = p0 + 8 * 130;
                p1[0] = acc[mt][nt][2] * INV32; p1[1] = acc[mt][nt][3] * INV32;
            }
        const float4* eg = (const float4*)(eps + (size_t)row0 * NE);
        #pragma unroll
        for (int i4 = 0; i4 < 8; ++i4) {
            int u = tid + 256 * i4;                 // 0..2047
            float4 v = eg[u];
            int r = u >> 4, e = (u & 15) * 4;
            float* d = Es + r * 66 + e;
            d[0] = v.x; d[1] = v.y; d[2] = v.z; d[3] = v.w;
        }
    }
    __syncthreads();

    // per-row top-2 (tid < 128 holds row r's result in regs)
    int i1 = 0, i2 = 0;
    float p1v = 0.f, p2v = 0.f;
    if (tid < BM) {
        const float* lg = Cs + tid * 130;
        const float* er = Es + tid * 66;
        const float NEG = __int_as_float(0xff800000);
        float m1 = NEG, m2 = NEG;
        #pragma unroll
        for (int e = 0; e < NE; ++e) {
            float v = lg[e] + er[e] * softplusf(lg[e + 64]);
            if (v > m1) { m2 = m1; i2 = i1; m1 = v; i1 = e; }
            else if (v > m2) { m2 = v; i2 = e; }
        }
        float ee = expf(m2 - m1);
        p1v = 1.0f / (1.0f + ee);
        p2v = ee * p1v;
        if (write_idx) {
            const size_t n = (size_t)row0 + tid;
            idx_out[n * 2 + 0] = (float)i1;
            idx_out[n * 2 + 1] = (float)i2;
        }
    }
    __syncthreads();   // done reading Cs/Es

    // assemble output block in smem (reuse Cs space): zero, scatter, store
    float* Os = (float*)smem;                    // [128][64] = 32768 B
    {
        float4 z = make_float4(0.f, 0.f, 0.f, 0.f);
        float4* oz = (float4*)Os;
        #pragma unroll
        for (int i = 0; i < 8; ++i) oz[tid + 256 * i] = z;
    }
    __syncthreads();
    if (tid < BM) {
        Os[tid * NE + i1] = p1v;
        Os[tid * NE + i2] = p2v;
    }
    __syncthreads();
    {
        float4* od = (float4*)(out + (size_t)row0 * NE);
        const float4* os4 = (const float4*)Os;
        #pragma unroll
        for (int i = 0; i < 8; ++i) od[tid + 256 * i] = os4[tid + 256 * i];
    }
}

extern "C" void kernel_launch(void* const* d_in, const int* in_sizes, int n_in,
                              void* d_out, int out_size)
{
    const float* x   = (const float*)d_in[0];
    const float* wr  = (const float*)d_in[1];
    const float* wn  = (const float*)d_in[2];
    const float* eps = (const float*)d_in[3];
    float* out = (float*)d_out;

    const int N = in_sizes[3] / NE;
    const int write_idx = (out_size >= N * NE + N * 2) ? 1 : 0;
    float* idx_out = out + (size_t)N * NE;

    prep_weights<<<(128 * DK / 4) / 256, 256>>>(wr, wn);

    cudaFuncSetAttribute(router_gemm,
                         cudaFuncAttributeMaxDynamicSharedMemorySize, SMEM_BYTES);
    router_gemm<<<N / BM, 256, SMEM_BYTES>>>(x, eps, out, idx_out, write_idx);
}

// round 16
// speedup vs baseline: 1.2253x; 1.1402x over previous
#include <cuda_runtime.h>
#include <cuda_fp16.h>
#include <cstdint>

// TopKNoisyRouter: fused dual GEMM [N,1024]x[1024,128], fp16 2-way split
// (3 HMMA products, fp32 accum, W pre-scaled by 32). r12 mainloop verbatim
// (KC=32, A 2-buf, B 3-buf ring at cp.async.cg distance 2, warp-parity
// k-step stagger, ldsm/MMA interleave, hoisted cp.async addressing).
// r15's .ca experiment reverted to .cg (the .ca L1 path slowed the whole
// ring). Kept from r15: single-write output epilogue (no startup
// zero-fill; block assembled in smem, stored once) and vectorized prep.
// 2 CTAs/SM. Fused noisy-top-2 + softmax epilogue.

#define DK 1024
#define NE 64
#define BM 128
#define KC 32
#define NCHUNK (DK / KC)      // 32
#define PLANE 8192            // 128 rows x 32 fp16 (64B rows)
#define OFF_B (4 * PLANE)     // A: 2 bufs x 2 planes; B: 3 bufs x 2 planes
#define SMEM_BYTES 100352     // max(gemm 80KB, epilogue staging)

__device__ __half g_w[2][128 * DK];   // fp16(32w), fp16(32w - hi); K-major

__device__ __forceinline__ uint32_t smem_u32(const void* p) {
    uint32_t a;
    asm("{ .reg .u64 t; cvta.to.shared.u64 t, %1; cvt.u32.u64 %0, t; }" : "=r"(a) : "l"(p));
    return a;
}
__device__ __forceinline__ uint32_t swz32(uint32_t r, uint32_t c) {
    return (r >> 1) * 128 + (r & 1) * 64 + (c ^ (((r >> 1) & 3) << 4));
}
__device__ __forceinline__ void cp16(uint32_t dst, const void* src) {
    asm volatile("cp.async.cg.shared.global [%0], [%1], 16;" :: "r"(dst), "l"(src));
}
__device__ __forceinline__ void ldsm4(uint32_t& r0, uint32_t& r1, uint32_t& r2,
                                      uint32_t& r3, uint32_t addr) {
    asm volatile("ldmatrix.sync.aligned.m8n8.x4.shared.b16 {%0,%1,%2,%3}, [%4];"
                 : "=r"(r0), "=r"(r1), "=r"(r2), "=r"(r3) : "r"(addr));
}
__device__ __forceinline__ void mma16816(float* c, const uint32_t* a,
                                         uint32_t b0, uint32_t b1) {
    asm volatile("mma.sync.aligned.m16n8k16.row.col.f32.f16.f16.f32 "
                 "{%0,%1,%2,%3}, {%4,%5,%6,%7}, {%8,%9}, {%0,%1,%2,%3};"
                 : "+f"(c[0]), "+f"(c[1]), "+f"(c[2]), "+f"(c[3])
                 : "r"(a[0]), "r"(a[1]), "r"(a[2]), "r"(a[3]), "r"(b0), "r"(b1));
}
__device__ __forceinline__ float softplusf(float v) {
    return fmaxf(v, 0.0f) + log1pf(expf(-fabsf(v)));
}
__device__ __forceinline__ uint32_t h2u(__half2 h) {
    union { __half2 h; uint32_t u; } v; v.h = h; return v.u;
}

__global__ void prep_weights(const float* __restrict__ wr, const float* __restrict__ wn) {
    int i4 = blockIdx.x * blockDim.x + threadIdx.x;   // 0 .. 32767 (x4 elems)
    int i = i4 * 4;
    int e = i >> 10, k = i & 1023;
    const float* src = (e < NE) ? (wr + e * DK + k) : (wn + (e - NE) * DK + k);
    float4 v4 = *(const float4*)src;
    float f[4] = {32.f * v4.x, 32.f * v4.y, 32.f * v4.z, 32.f * v4.w};
    __half h[4], l[4];
    #pragma unroll
    for (int j = 0; j < 4; ++j) {
        h[j] = __float2half_rn(f[j]);
        l[j] = __float2half_rn(f[j] - __half2float(h[j]));
    }
    *(uint2*)&g_w[0][i] = make_uint2(
        (uint32_t)__half_as_ushort(h[0]) | ((uint32_t)__half_as_ushort(h[1]) << 16),
        (uint32_t)__half_as_ushort(h[2]) | ((uint32_t)__half_as_ushort(h[3]) << 16));
    *(uint2*)&g_w[1][i] = make_uint2(
        (uint32_t)__half_as_ushort(l[0]) | ((uint32_t)__half_as_ushort(l[1]) << 16),
        (uint32_t)__half_as_ushort(l[2]) | ((uint32_t)__half_as_ushort(l[3]) << 16));
}

__global__ __launch_bounds__(256, 2)
void router_gemm(const float* __restrict__ x, const float* __restrict__ eps,
                 float* __restrict__ out, float* __restrict__ idx_out, int write_idx)
{
    extern __shared__ char smem[];
    const uint32_t sb = smem_u32(smem);
    const int tid = threadIdx.x;
    const int lane = tid & 31, wid = tid >> 5;
    const int wm = wid & 1, wq = wid >> 1;        // warp tile 64x32 at (wm*64, wq*32)
    const int row0 = blockIdx.x * BM;

    // ldmatrix per-lane address pieces
    const int rA = wm * 64 + (lane & 15);
    const uint32_t rowA = (uint32_t)((rA >> 1) * 128 + (rA & 1) * 64);
    const uint32_t xorA = (uint32_t)(((rA >> 1) & 3) << 4);
    const uint32_t cbA  = (uint32_t)((lane >> 4) * 16);
    const int rB = wq * 32 + (lane & 7) + ((lane >> 4) << 3);
    const uint32_t rowB = (uint32_t)((rB >> 1) * 128 + (rB & 1) * 64);
    const uint32_t xorB = (uint32_t)(((rB >> 1) & 3) << 4);
    const uint32_t cbB  = (uint32_t)(((lane >> 3) & 1) * 16);
    const int ksw = wid & 1;     // k-step stagger parity

    // x staging: thread covers row r_x, 16 floats at float-offset h_x
    const int r_x = tid >> 1;
    const int h_x = (tid & 1) * 16;
    const float* xbase = x + (size_t)(row0 + r_x) * DK + h_x;
    const uint32_t rowX = (uint32_t)((r_x >> 1) * 128 + (r_x & 1) * 64);
    const uint32_t xorX = (uint32_t)(((r_x >> 1) & 3) << 4);
    const uint32_t swX0 = rowX + (((uint32_t)(h_x * 2) +  0) ^ xorX);
    const uint32_t swX1 = rowX + (((uint32_t)(h_x * 2) + 16) ^ xorX);

    // hoisted cp.async per-thread addressing (4 copies of 16B per chunk)
    uint32_t bdst[4];
    const __half* bsrc[4];
    #pragma unroll
    for (int j = 0; j < 4; ++j) {
        const int u = tid + 256 * j;             // 0..1023
        const int s = u >> 9, rem = u & 511;
        const int n = rem >> 2, cu = (rem & 3) * 16;
        bdst[j] = sb + OFF_B + (uint32_t)s * PLANE + swz32((uint32_t)n, (uint32_t)cu);
        bsrc[j] = &g_w[s][n * DK + (cu >> 1)];
    }

    float acc[4][4][4];
    #pragma unroll
    for (int mt = 0; mt < 4; ++mt)
        #pragma unroll
        for (int nt = 0; nt < 4; ++nt)
            #pragma unroll
            for (int q = 0; q < 4; ++q) acc[mt][nt][q] = 0.f;

    // ---- prologue: x chunk0 -> regs; B chunks 0,1 -> cp.async (2 groups) ----
    float4 xr[4];
    #pragma unroll
    for (int i = 0; i < 4; ++i) xr[i] = *(const float4*)(xbase + 4 * i);
    #pragma unroll
    for (int j = 0; j < 4; ++j) cp16(bdst[j], bsrc[j]);
    asm volatile("cp.async.commit_group;" ::: "memory");
    #pragma unroll
    for (int j = 0; j < 4; ++j) cp16(bdst[j] + 2 * PLANE, bsrc[j] + KC);
    asm volatile("cp.async.commit_group;" ::: "memory");

    int br = 0;   // B read buffer (c % 3)
    int bp = 2;   // B prefetch buffer ((c+2) % 3)

    #pragma unroll 1
    for (int c = 0; c < NCHUNK; ++c) {
        const int b = c & 1;
        const int kn = ((c + 1) & (NCHUNK - 1)) * KC;   // next x chunk (wraps, safe)
        char* Ab = smem + (uint32_t)(b * 2) * PLANE;

        // ---- convert x regs (chunk c) -> A[b] (packed f16x2, STS.128);
        //      prefetch next x into regs ----
        {
            uint32_t hh[8], hl[8];
            #pragma unroll
            for (int i = 0; i < 4; ++i) {
                float4 f4 = xr[i];
                xr[i] = *(const float4*)(xbase + kn + 4 * i);
                __half2 a2 = __floats2half2_rn(f4.x, f4.y);
                __half2 b2 = __floats2half2_rn(f4.z, f4.w);
                float2 fa = __half22float2(a2), fb = __half22float2(b2);
                hh[2 * i]     = h2u(a2);
                hh[2 * i + 1] = h2u(b2);
                hl[2 * i]     = h2u(__floats2half2_rn(f4.x - fa.x, f4.y - fa.y));
                hl[2 * i + 1] = h2u(__floats2half2_rn(f4.z - fb.x, f4.w - fb.y));
            }
            *(uint4*)(Ab + swX0)         = make_uint4(hh[0], hh[1], hh[2], hh[3]);
            *(uint4*)(Ab + swX1)         = make_uint4(hh[4], hh[5], hh[6], hh[7]);
            *(uint4*)(Ab + PLANE + swX0) = make_uint4(hl[0], hl[1], hl[2], hl[3]);
            *(uint4*)(Ab + PLANE + swX1) = make_uint4(hl[4], hl[5], hl[6], hl[7]);
        }

        // B group for chunk c complete for THIS thread, then publish.
        asm volatile("cp.async.wait_group 1;" ::: "memory");
        __syncthreads();                         // A[b] + B[br] visible

        // ---- issue B chunk c+2 into buffer bp; commit ALWAYS (empty on
        //      tail) to keep group accounting exact ----
        if (c + 2 < NCHUNK) {
            const int kB = (c + 2) * KC;
            const uint32_t bb = (uint32_t)(bp * 2) * PLANE;
            #pragma unroll
            for (int j = 0; j < 4; ++j) cp16(bdst[j] + bb, bsrc[j] + kB);
        }
        asm volatile("cp.async.commit_group;" ::: "memory");

        // ---- MMA: 3 split products over 2 k16 steps, staggered by warp
        //      parity; ldsm groups interleaved with MMA groups ----
        const uint32_t Ah = sb + (uint32_t)(b * 2) * PLANE;
        const uint32_t Al = Ah + PLANE;
        const uint32_t Bh = sb + OFF_B + (uint32_t)(br * 2) * PLANE;
        const uint32_t Bl = Bh + PLANE;
        #pragma unroll
        for (int t = 0; t < 2; ++t) {
            const int ks = t ^ ksw;              // even warps 0,1; odd 1,0
            const uint32_t kb = (uint32_t)(ks * 32);
            const uint32_t ca = (kb + cbA) ^ xorA;
            const uint32_t cc = (kb + cbB) ^ xorB;
            uint32_t a[4][4], bh[8], bl[8];
            // group 1: A-hi + B-hi, then hh product
            #pragma unroll
            for (int mt = 0; mt < 4; ++mt)
                ldsm4(a[mt][0], a[mt][1], a[mt][2], a[mt][3], Ah + rowA + mt * 1024 + ca);
            ldsm4(bh[0], bh[1], bh[2], bh[3], Bh + rowB + cc);
            ldsm4(bh[4], bh[5], bh[6], bh[7], Bh + rowB + 1024 + cc);
            #pragma unroll
            for (int mt = 0; mt < 4; ++mt)
                #pragma unroll
                for (int nt = 0; nt < 4; ++nt)
                    mma16816(acc[mt][nt], a[mt], bh[2 * nt], bh[2 * nt + 1]);
            // group 2: B-lo, then hl product
            ldsm4(bl[0], bl[1], bl[2], bl[3], Bl + rowB + cc);
            ldsm4(bl[4], bl[5], bl[6], bl[7], Bl + rowB + 1024 + cc);
            #pragma unroll
            for (int mt = 0; mt < 4; ++mt)
                #pragma unroll
                for (int nt = 0; nt < 4; ++nt)
                    mma16816(acc[mt][nt], a[mt], bl[2 * nt], bl[2 * nt + 1]);
            // group 3: A-lo, then lh product
            #pragma unroll
            for (int mt = 0; mt < 4; ++mt)
                ldsm4(a[mt][0], a[mt][1], a[mt][2], a[mt][3], Al + rowA + mt * 1024 + ca);
            #pragma unroll
            for (int mt = 0; mt < 4; ++mt)
                #pragma unroll
                for (int nt = 0; nt < 4; ++nt)
                    mma16816(acc[mt][nt], a[mt], bh[2 * nt], bh[2 * nt + 1]);
        }

        br = (br == 2) ? 0 : br + 1;
        bp = (bp == 2) ? 0 : bp + 1;
    }
    __syncthreads();

    // ---- epilogue: stage C (scaled 1/32) + eps, top-2, then single-write
    //      of the fully-assembled [128][64] output block ----
    float* Cs = (float*)smem;                    // [128][130] = 66560 B
    float* Es = (float*)(smem + 66560);          // [128][66]  = 33792 B
    {
        const float INV32 = 0.03125f;
        const int crow = wm * 64 + (lane >> 2);
        const int ccol = wq * 32 + (lane & 3) * 2;
        #pragma unroll
        for (int mt = 0; mt < 4; ++mt)
            #pragma unroll
            for (int nt = 0; nt < 4; ++nt) {
                float* p0 = Cs + (crow + mt * 16) * 130 + ccol + nt * 8;
                p0[0] = acc[mt][nt][0] * INV32; p0[1] = acc[mt][nt][1] * INV32;
                float* p1 = p0 + 8 * 130;
                p1[0] = acc[mt][nt][2] * INV32; p1[1] = acc[mt][nt][3] * INV32;
            }
        const float4* eg = (const float4*)(eps + (size_t)row0 * NE);
        #pragma unroll
        for (int i4 = 0; i4 < 8; ++i4) {
            int u = tid + 256 * i4;                 // 0..2047
            float4 v = eg[u];
            int r = u >> 4, e = (u & 15) * 4;
            float* d = Es + r * 66 + e;
            d[0] = v.x; d[1] = v.y; d[2] = v.z; d[3] = v.w;
        }
    }
    __syncthreads();

    // per-row top-2 (tid < 128 holds row r's result in regs)
    int i1 = 0, i2 = 0;
    float p1v = 0.f, p2v = 0.f;
    if (tid < BM) {
        const float* lg = Cs + tid * 130;
        const float* er = Es + tid * 66;
        const float NEG = __int_as_float(0xff800000);
        float m1 = NEG, m2 = NEG;
        #pragma unroll
        for (int e = 0; e < NE; ++e) {
            float v = lg[e] + er[e] * softplusf(lg[e + 64]);
            if (v > m1) { m2 = m1; i2 = i1; m1 = v; i1 = e; }
            else if (v > m2) { m2 = v; i2 = e; }
        }
        float ee = expf(m2 - m1);
        p1v = 1.0f / (1.0f + ee);
        p2v = ee * p1v;
        if (write_idx) {
            const size_t n = (size_t)row0 + tid;
            idx_out[n * 2 + 0] = (float)i1;
            idx_out[n * 2 + 1] = (float)i2;
        }
    }
    __syncthreads();   // done reading Cs/Es

    // assemble output block in smem (reuse Cs space): zero, scatter, store
    float* Os = (float*)smem;                    // [128][64] = 32768 B
    {
        float4 z = make_float4(0.f, 0.f, 0.f, 0.f);
        float4* oz = (float4*)Os;
        #pragma unroll
        for (int i = 0; i < 8; ++i) oz[tid + 256 * i] = z;
    }
    __syncthreads();
    if (tid < BM) {
        Os[tid * NE + i1] = p1v;
        Os[tid * NE + i2] = p2v;
    }
    __syncthreads();
    {
        float4* od = (float4*)(out + (size_t)row0 * NE);
        const float4* os4 = (const float4*)Os;
        #pragma unroll
        for (int i = 0; i < 8; ++i) od[tid + 256 * i] = os4[tid + 256 * i];
    }
}

extern "C" void kernel_launch(void* const* d_in, const int* in_sizes, int n_in,
                              void* d_out, int out_size)
{
    const float* x   = (const float*)d_in[0];
    const float* wr  = (const float*)d_in[1];
    const float* wn  = (const float*)d_in[2];
    const float* eps = (const float*)d_in[3];
    float* out = (float*)d_out;

    const int N = in_sizes[3] / NE;
    const int write_idx = (out_size >= N * NE + N * 2) ? 1 : 0;
    float* idx_out = out + (size_t)N * NE;

    prep_weights<<<(128 * DK / 4) / 256, 256>>>(wr, wn);

    cudaFuncSetAttribute(router_gemm,
                         cudaFuncAttributeMaxDynamicSharedMemorySize, SMEM_BYTES);
    router_gemm<<<N / BM, 256, SMEM_BYTES>>>(x, eps, out, idx_out, write_idx);
}

// round 17
// speedup vs baseline: 1.2568x; 1.0257x over previous
#include <cuda_runtime.h>
#include <cuda_fp16.h>
#include <cstdint>

// TopKNoisyRouter: fused dual GEMM [N,1024]x[1024,128], fp16 2-way split
// (3 HMMA products, fp32 accum, W pre-scaled by 32). Best-known config =
// round-12 router_gemm VERBATIM (KC=32, A 2-buf, B 3-buf ring, cp.async.cg
// distance 2, warp-parity k-step stagger, ldsm/MMA interleave, hoisted
// cp.async addressing, startup zero-fill + direct scatter epilogue) plus
// the vectorized prep_weights (float4, 4 elems/thread) — the only
// individually-validated improvement from rounds 15/16.
// 2 CTAs/SM. Fused noisy-top-2 + softmax epilogue.

#define DK 1024
#define NE 64
#define BM 128
#define KC 32
#define NCHUNK (DK / KC)      // 32
#define PLANE 8192            // 128 rows x 32 fp16 (64B rows)
#define OFF_B (4 * PLANE)     // A: 2 bufs x 2 planes; B: 3 bufs x 2 planes
#define SMEM_BYTES 100352     // max(gemm 80KB, epilogue C+eps staging 100KB)

__device__ __half g_w[2][128 * DK];   // fp16(32w), fp16(32w - hi); K-major

__device__ __forceinline__ uint32_t smem_u32(const void* p) {
    uint32_t a;
    asm("{ .reg .u64 t; cvta.to.shared.u64 t, %1; cvt.u32.u64 %0, t; }" : "=r"(a) : "l"(p));
    return a;
}
__device__ __forceinline__ uint32_t swz32(uint32_t r, uint32_t c) {
    return (r >> 1) * 128 + (r & 1) * 64 + (c ^ (((r >> 1) & 3) << 4));
}
__device__ __forceinline__ void cp16(uint32_t dst, const void* src) {
    asm volatile("cp.async.cg.shared.global [%0], [%1], 16;" :: "r"(dst), "l"(src));
}
__device__ __forceinline__ void ldsm4(uint32_t& r0, uint32_t& r1, uint32_t& r2,
                                      uint32_t& r3, uint32_t addr) {
    asm volatile("ldmatrix.sync.aligned.m8n8.x4.shared.b16 {%0,%1,%2,%3}, [%4];"
                 : "=r"(r0), "=r"(r1), "=r"(r2), "=r"(r3) : "r"(addr));
}
__device__ __forceinline__ void mma16816(float* c, const uint32_t* a,
                                         uint32_t b0, uint32_t b1) {
    asm volatile("mma.sync.aligned.m16n8k16.row.col.f32.f16.f16.f32 "
                 "{%0,%1,%2,%3}, {%4,%5,%6,%7}, {%8,%9}, {%0,%1,%2,%3};"
                 : "+f"(c[0]), "+f"(c[1]), "+f"(c[2]), "+f"(c[3])
                 : "r"(a[0]), "r"(a[1]), "r"(a[2]), "r"(a[3]), "r"(b0), "r"(b1));
}
__device__ __forceinline__ float softplusf(float v) {
    return fmaxf(v, 0.0f) + log1pf(expf(-fabsf(v)));
}
__device__ __forceinline__ uint32_t h2u(__half2 h) {
    union { __half2 h; uint32_t u; } v; v.h = h; return v.u;
}

__global__ void prep_weights(const float* __restrict__ wr, const float* __restrict__ wn) {
    int i4 = blockIdx.x * blockDim.x + threadIdx.x;   // 0 .. 32767 (x4 elems)
    int i = i4 * 4;
    int e = i >> 10, k = i & 1023;
    const float* src = (e < NE) ? (wr + e * DK + k) : (wn + (e - NE) * DK + k);
    float4 v4 = *(const float4*)src;
    float f[4] = {32.f * v4.x, 32.f * v4.y, 32.f * v4.z, 32.f * v4.w};
    __half h[4], l[4];
    #pragma unroll
    for (int j = 0; j < 4; ++j) {
        h[j] = __float2half_rn(f[j]);
        l[j] = __float2half_rn(f[j] - __half2float(h[j]));
    }
    *(uint2*)&g_w[0][i] = make_uint2(
        (uint32_t)__half_as_ushort(h[0]) | ((uint32_t)__half_as_ushort(h[1]) << 16),
        (uint32_t)__half_as_ushort(h[2]) | ((uint32_t)__half_as_ushort(h[3]) << 16));
    *(uint2*)&g_w[1][i] = make_uint2(
        (uint32_t)__half_as_ushort(l[0]) | ((uint32_t)__half_as_ushort(l[1]) << 16),
        (uint32_t)__half_as_ushort(l[2]) | ((uint32_t)__half_as_ushort(l[3]) << 16));
}

__global__ __launch_bounds__(256, 2)
void router_gemm(const float* __restrict__ x, const float* __restrict__ eps,
                 float* __restrict__ out, float* __restrict__ idx_out, int write_idx)
{
    extern __shared__ char smem[];
    const uint32_t sb = smem_u32(smem);
    const int tid = threadIdx.x;
    const int lane = tid & 31, wid = tid >> 5;
    const int wm = wid & 1, wq = wid >> 1;        // warp tile 64x32 at (wm*64, wq*32)
    const int row0 = blockIdx.x * BM;

    // coalesced zero-fill of this block's output tile [128 x 64]
    {
        float4 z = make_float4(0.f, 0.f, 0.f, 0.f);
        float4* ot = (float4*)(out + (size_t)row0 * NE);
        #pragma unroll
        for (int i = 0; i < 8; ++i) ot[tid + 256 * i] = z;
    }

    // ldmatrix per-lane address pieces
    const int rA = wm * 64 + (lane & 15);
    const uint32_t rowA = (uint32_t)((rA >> 1) * 128 + (rA & 1) * 64);
    const uint32_t xorA = (uint32_t)(((rA >> 1) & 3) << 4);
    const uint32_t cbA  = (uint32_t)((lane >> 4) * 16);
    const int rB = wq * 32 + (lane & 7) + ((lane >> 4) << 3);
    const uint32_t rowB = (uint32_t)((rB >> 1) * 128 + (rB & 1) * 64);
    const uint32_t xorB = (uint32_t)(((rB >> 1) & 3) << 4);
    const uint32_t cbB  = (uint32_t)(((lane >> 3) & 1) * 16);
    const int ksw = wid & 1;     // k-step stagger parity

    // x staging: thread covers row r_x, 16 floats at float-offset h_x
    const int r_x = tid >> 1;
    const int h_x = (tid & 1) * 16;
    const float* xbase = x + (size_t)(row0 + r_x) * DK + h_x;
    const uint32_t rowX = (uint32_t)((r_x >> 1) * 128 + (r_x & 1) * 64);
    const uint32_t xorX = (uint32_t)(((r_x >> 1) & 3) << 4);
    const uint32_t swX0 = rowX + (((uint32_t)(h_x * 2) +  0) ^ xorX);
    const uint32_t swX1 = rowX + (((uint32_t)(h_x * 2) + 16) ^ xorX);

    // hoisted cp.async per-thread addressing (4 copies of 16B per chunk)
    uint32_t bdst[4];
    const __half* bsrc[4];
    #pragma unroll
    for (int j = 0; j < 4; ++j) {
        const int u = tid + 256 * j;             // 0..1023
        const int s = u >> 9, rem = u & 511;
        const int n = rem >> 2, cu = (rem & 3) * 16;
        bdst[j] = sb + OFF_B + (uint32_t)s * PLANE + swz32((uint32_t)n, (uint32_t)cu);
        bsrc[j] = &g_w[s][n * DK + (cu >> 1)];
    }

    float acc[4][4][4];
    #pragma unroll
    for (int mt = 0; mt < 4; ++mt)
        #pragma unroll
        for (int nt = 0; nt < 4; ++nt)
            #pragma unroll
            for (int q = 0; q < 4; ++q) acc[mt][nt][q] = 0.f;

    // ---- prologue: x chunk0 -> regs; B chunks 0,1 -> cp.async (2 groups) ----
    float4 xr[4];
    #pragma unroll
    for (int i = 0; i < 4; ++i) xr[i] = *(const float4*)(xbase + 4 * i);
    #pragma unroll
    for (int j = 0; j < 4; ++j) cp16(bdst[j], bsrc[j]);
    asm volatile("cp.async.commit_group;" ::: "memory");
    #pragma unroll
    for (int j = 0; j < 4; ++j) cp16(bdst[j] + 2 * PLANE, bsrc[j] + KC);
    asm volatile("cp.async.commit_group;" ::: "memory");

    int br = 0;   // B read buffer (c % 3)
    int bp = 2;   // B prefetch buffer ((c+2) % 3)

    #pragma unroll 1
    for (int c = 0; c < NCHUNK; ++c) {
        const int b = c & 1;
        const int kn = ((c + 1) & (NCHUNK - 1)) * KC;   // next x chunk (wraps, safe)
        char* Ab = smem + (uint32_t)(b * 2) * PLANE;

        // ---- convert x regs (chunk c) -> A[b] (packed f16x2, STS.128);
        //      prefetch next x into regs ----
        {
            uint32_t hh[8], hl[8];
            #pragma unroll
            for (int i = 0; i < 4; ++i) {
                float4 f4 = xr[i];
                xr[i] = *(const float4*)(xbase + kn + 4 * i);
                __half2 a2 = __floats2half2_rn(f4.x, f4.y);
                __half2 b2 = __floats2half2_rn(f4.z, f4.w);
                float2 fa = __half22float2(a2), fb = __half22float2(b2);
                hh[2 * i]     = h2u(a2);
                hh[2 * i + 1] = h2u(b2);
                hl[2 * i]     = h2u(__floats2half2_rn(f4.x - fa.x, f4.y - fa.y));
                hl[2 * i + 1] = h2u(__floats2half2_rn(f4.z - fb.x, f4.w - fb.y));
            }
            *(uint4*)(Ab + swX0)         = make_uint4(hh[0], hh[1], hh[2], hh[3]);
            *(uint4*)(Ab + swX1)         = make_uint4(hh[4], hh[5], hh[6], hh[7]);
            *(uint4*)(Ab + PLANE + swX0) = make_uint4(hl[0], hl[1], hl[2], hl[3]);
            *(uint4*)(Ab + PLANE + swX1) = make_uint4(hl[4], hl[5], hl[6], hl[7]);
        }

        // B group for chunk c complete for THIS thread, then publish.
        asm volatile("cp.async.wait_group 1;" ::: "memory");
        __syncthreads();                         // A[b] + B[br] visible

        // ---- issue B chunk c+2 into buffer bp; commit ALWAYS (empty on
        //      tail) to keep group accounting exact ----
        if (c + 2 < NCHUNK) {
            const int kB = (c + 2) * KC;
            const uint32_t bb = (uint32_t)(bp * 2) * PLANE;
            #pragma unroll
            for (int j = 0; j < 4; ++j) cp16(bdst[j] + bb, bsrc[j] + kB);
        }
        asm volatile("cp.async.commit_group;" ::: "memory");

        // ---- MMA: 3 split products over 2 k16 steps, staggered by warp
        //      parity; ldsm groups interleaved with MMA groups ----
        const uint32_t Ah = sb + (uint32_t)(b * 2) * PLANE;
        const uint32_t Al = Ah + PLANE;
        const uint32_t Bh = sb + OFF_B + (uint32_t)(br * 2) * PLANE;
        const uint32_t Bl = Bh + PLANE;
        #pragma unroll
        for (int t = 0; t < 2; ++t) {
            const int ks = t ^ ksw;              // even warps 0,1; odd 1,0
            const uint32_t kb = (uint32_t)(ks * 32);
            const uint32_t ca = (kb + cbA) ^ xorA;
            const uint32_t cc = (kb + cbB) ^ xorB;
            uint32_t a[4][4], bh[8], bl[8];
            // group 1: A-hi + B-hi, then hh product
            #pragma unroll
            for (int mt = 0; mt < 4; ++mt)
                ldsm4(a[mt][0], a[mt][1], a[mt][2], a[mt][3], Ah + rowA + mt * 1024 + ca);
            ldsm4(bh[0], bh[1], bh[2], bh[3], Bh + rowB + cc);
            ldsm4(bh[4], bh[5], bh[6], bh[7], Bh + rowB + 1024 + cc);
            #pragma unroll
            for (int mt = 0; mt < 4; ++mt)
                #pragma unroll
                for (int nt = 0; nt < 4; ++nt)
                    mma16816(acc[mt][nt], a[mt], bh[2 * nt], bh[2 * nt + 1]);
            // group 2: B-lo, then hl product
            ldsm4(bl[0], bl[1], bl[2], bl[3], Bl + rowB + cc);
            ldsm4(bl[4], bl[5], bl[6], bl[7], Bl + rowB + 1024 + cc);
            #pragma unroll
            for (int mt = 0; mt < 4; ++mt)
                #pragma unroll
                for (int nt = 0; nt < 4; ++nt)
                    mma16816(acc[mt][nt], a[mt], bl[2 * nt], bl[2 * nt + 1]);
            // group 3: A-lo, then lh product
            #pragma unroll
            for (int mt = 0; mt < 4; ++mt)
                ldsm4(a[mt][0], a[mt][1], a[mt][2], a[mt][3], Al + rowA + mt * 1024 + ca);
            #pragma unroll
            for (int mt = 0; mt < 4; ++mt)
                #pragma unroll
                for (int nt = 0; nt < 4; ++nt)
                    mma16816(acc[mt][nt], a[mt], bh[2 * nt], bh[2 * nt + 1]);
        }

        br = (br == 2) ? 0 : br + 1;
        bp = (bp == 2) ? 0 : bp + 1;
    }
    __syncthreads();

    // ---- stage C (scaled 1/32) + eps to smem, fused top-2 epilogue ----
    float* Cs = (float*)smem;                    // [128][130]
    float* Es = (float*)(smem + 66560);          // [128][66]
    {
        const float INV32 = 0.03125f;
        const int crow = wm * 64 + (lane >> 2);
        const int ccol = wq * 32 + (lane & 3) * 2;
        #pragma unroll
        for (int mt = 0; mt < 4; ++mt)
            #pragma unroll
            for (int nt = 0; nt < 4; ++nt) {
                float* p0 = Cs + (crow + mt * 16) * 130 + ccol + nt * 8;
                p0[0] = acc[mt][nt][0] * INV32; p0[1] = acc[mt][nt][1] * INV32;
                float* p1 = p0 + 8 * 130;
                p1[0] = acc[mt][nt][2] * INV32; p1[1] = acc[mt][nt][3] * INV32;
            }
        const float4* eg = (const float4*)(eps + (size_t)row0 * NE);
        #pragma unroll
        for (int i4 = 0; i4 < 8; ++i4) {
            int u = tid + 256 * i4;                 // 0..2047
            float4 v = eg[u];
            int r = u >> 4, e = (u & 15) * 4;
            float* d = Es + r * 66 + e;
            d[0] = v.x; d[1] = v.y; d[2] = v.z; d[3] = v.w;
        }
    }
    __syncthreads();

    if (tid < BM) {
        const int r = tid;
        const size_t n = (size_t)row0 + r;
        const float* lg = Cs + r * 130;
        const float* er = Es + r * 66;
        const float NEG = __int_as_float(0xff800000);
        float m1 = NEG, m2 = NEG; int i1 = 0, i2 = 0;
        #pragma unroll
        for (int e = 0; e < NE; ++e) {
            float v = lg[e] + er[e] * softplusf(lg[e + 64]);
            if (v > m1) { m2 = m1; i2 = i1; m1 = v; i1 = e; }
            else if (v > m2) { m2 = v; i2 = e; }
        }
        float ee = expf(m2 - m1);
        float inv = 1.0f / (1.0f + ee);
        out[n * NE + i1] = inv;
        out[n * NE + i2] = ee * inv;
        if (write_idx) {
            idx_out[n * 2 + 0] = (float)i1;
            idx_out[n * 2 + 1] = (float)i2;
        }
    }
}

extern "C" void kernel_launch(void* const* d_in, const int* in_sizes, int n_in,
                              void* d_out, int out_size)
{
    const float* x   = (const float*)d_in[0];
    const float* wr  = (const float*)d_in[1];
    const float* wn  = (const float*)d_in[2];
    const float* eps = (const float*)d_in[3];
    float* out = (float*)d_out;

    const int N = in_sizes[3] / NE;
    const int write_idx = (out_size >= N * NE + N * 2) ? 1 : 0;
    float* idx_out = out + (size_t)N * NE;

    prep_weights<<<(128 * DK / 4) / 256, 256>>>(wr, wn);

    cudaFuncSetAttribute(router_gemm,
                         cudaFuncAttributeMaxDynamicSharedMemorySize, SMEM_BYTES);
    router_gemm<<<N / BM, 256, SMEM_BYTES>>>(x, eps, out, idx_out, write_idx);
}